// round 14
// baseline (speedup 1.0000x reference)
#include <cuda_runtime.h>
#include <cuda_fp16.h>
#include <cuda_bf16.h>

#define N_NODES 10000
#define E_EDGES 160000
#define EP (E_EDGES + N_NODES)   // 170000 (even)
#define IN_CH 128
#define EMB 64
#define HEADS 12
#define HD (HEADS * EMB)          // 768
#define NEG_SLOPE 0.2f
#define NB 148                    // blocks (<= 152 SMs: all co-resident)
#define NT 768
#define NTILES ((N_NODES + 15) / 16)   // 625

// ---- scratch (device globals; no allocation allowed) ----
__device__ float    g_emb[N_NODES * EMB];
__device__ __half   g_hh16[N_NODES * HD];
__device__ float    g_asrc[N_NODES * HEADS];
__device__ float    g_adst[N_NODES * HEADS];
__device__ float    g_denom[N_NODES * HEADS];
__device__ float    g_eexp[EP * HEADS];
__device__ float    g_agg[N_NODES * EMB];
__device__ unsigned g_bar_count[8];
__device__ unsigned g_bar_gen[8];

// ---- f32x2 packed-FMA helpers ----
__device__ __forceinline__ unsigned long long pack2(float lo, float hi) {
    unsigned long long r;
    asm("mov.b64 %0, {%1, %2};" : "=l"(r) : "f"(lo), "f"(hi));
    return r;
}
__device__ __forceinline__ void unpack2(unsigned long long v, float& lo, float& hi) {
    asm("mov.b64 {%0, %1}, %2;" : "=f"(lo), "=f"(hi) : "l"(v));
}
__device__ __forceinline__ void fma2(unsigned long long& d,
                                     unsigned long long a, unsigned long long b) {
    asm("fma.rn.f32x2 %0, %1, %2, %0;" : "+l"(d) : "l"(a), "l"(b));
}

// ---- device-wide sense-reversal barrier (graph-replay safe: gen monotonic,
//      count self-resets; all NB blocks guaranteed co-resident) ----
__device__ __forceinline__ void grid_barrier(int i) {
    __syncthreads();
    if (threadIdx.x == 0) {
        __threadfence();
        unsigned g = ((volatile unsigned*)g_bar_gen)[i];
        unsigned prev = atomicAdd(&g_bar_count[i], 1u);
        if (prev == NB - 1) {
            g_bar_count[i] = 0;
            __threadfence();
            atomicAdd(&g_bar_gen[i], 1u);
        } else {
            while (((volatile unsigned*)g_bar_gen)[i] == g) __nanosleep(64);
        }
    }
    __syncthreads();
}

__global__ void __launch_bounds__(NT, 1)
k_fused(const float* __restrict__ x,
        const int*   __restrict__ ei,
        const float* __restrict__ We,
        const float* __restrict__ be,
        const float* __restrict__ W,
        const float* __restrict__ att_src,
        const float* __restrict__ att_dst,
        const float* __restrict__ bias,
        float* __restrict__ out) {
    extern __shared__ float dyn[];
    int t = threadIdx.x;
    int gt = blockIdx.x * NT + t;            // 0..113663

    // ===== phase A: zero scratch + emb = relu(x@We+be) =====
    {
        float4 z = make_float4(0.f, 0.f, 0.f, 0.f);
        for (int i = gt; i < (N_NODES * EMB) / 4; i += NB * NT) ((float4*)g_agg)[i] = z;
        if (gt < (N_NODES * HEADS) / 4) ((float4*)g_denom)[gt] = z;

        int sb = t >> 6;                     // sub-block 0..11 (64 threads each)
        int st = t & 63;                     // channel
        int tile = blockIdx.x * 12 + sb;     // 0..1775 (625 valid)
        float* sx = dyn + sb * (IN_CH * 16); // [128][16] per sub-block (8KB)
        bool valid = tile < NTILES;
        int n0 = tile * 16;
        if (valid) {
            for (int idx = st; idx < 16 * IN_CH; idx += 64) {
                int i = idx >> 7, k = idx & 127;
                sx[k * 16 + i] = x[(n0 + i) * IN_CH + k];
            }
        }
        __syncthreads();
        if (valid) {
            float b = be[st];
            unsigned long long acc[8];
            unsigned long long binit = pack2(b, b);
#pragma unroll
            for (int j = 0; j < 8; j++) acc[j] = binit;
            for (int k = 0; k < IN_CH; k++) {
                float wv = We[k * EMB + st];
                unsigned long long w2 = pack2(wv, wv);
#pragma unroll
                for (int j = 0; j < 8; j++)
                    fma2(acc[j], *(const unsigned long long*)&sx[k * 16 + 2 * j], w2);
            }
#pragma unroll
            for (int j = 0; j < 8; j++) {
                float lo, hi;
                unpack2(acc[j], lo, hi);
                g_emb[(n0 + 2 * j) * EMB + st]     = fmaxf(lo, 0.f);
                g_emb[(n0 + 2 * j + 1) * EMB + st] = fmaxf(hi, 0.f);
            }
        }
    }
    grid_barrier(0);

    // ===== phase B: hh = emb@W (fp16) + per-head logits =====
    {
        float* se   = dyn;                   // [64][16]
        float* ssrc = dyn + EMB * 16;        // [16][12]
        float* sdst = ssrc + 16 * HEADS;
        float as = att_src[t], ad = att_dst[t];
        int hh_ = t >> 6;                    // head of this warp-pair channel

        for (int tile = blockIdx.x; tile < NTILES; tile += NB) {
            int n0 = tile * 16;
            for (int idx = t; idx < 16 * EMB; idx += NT) {
                int i = idx >> 6, k = idx & 63;
                se[k * 16 + i] = g_emb[(n0 + i) * EMB + k];
            }
            if (t < 16 * HEADS) { ssrc[t] = 0.f; sdst[t] = 0.f; }
            __syncthreads();

            unsigned long long acc[8];
#pragma unroll
            for (int j = 0; j < 8; j++) acc[j] = 0ull;
            for (int k = 0; k < EMB; k++) {
                float wv = W[k * HD + t];
                unsigned long long w2 = pack2(wv, wv);
#pragma unroll
                for (int j = 0; j < 8; j++)
                    fma2(acc[j], *(const unsigned long long*)&se[k * 16 + 2 * j], w2);
            }
            float av[16];
#pragma unroll
            for (int j = 0; j < 8; j++) unpack2(acc[j], av[2 * j], av[2 * j + 1]);

#pragma unroll
            for (int i = 0; i < 16; i++) {
                g_hh16[(size_t)(n0 + i) * HD + t] = __float2half_rn(av[i]);
                float ps = av[i] * as;
                float pd = av[i] * ad;
#pragma unroll
                for (int off = 16; off; off >>= 1) {
                    ps += __shfl_down_sync(0xffffffffu, ps, off);
                    pd += __shfl_down_sync(0xffffffffu, pd, off);
                }
                if ((t & 31) == 0) {
                    atomicAdd(&ssrc[i * HEADS + hh_], ps);
                    atomicAdd(&sdst[i * HEADS + hh_], pd);
                }
            }
            __syncthreads();
            if (t < 16 * HEADS) {
                int i = t / HEADS, h = t - i * HEADS;
                g_asrc[(n0 + i) * HEADS + h] = ssrc[i * HEADS + h];
                g_adst[(n0 + i) * HEADS + h] = sdst[i * HEADS + h];
            }
            __syncthreads();                 // protect smem before next tile
        }
    }
    grid_barrier(1);

    // ===== phase C: per-(edge,head) exp + atomic denom =====
    for (int idx = gt; idx < EP * HEADS; idx += NB * NT) {
        int e = idx / HEADS, h = idx - e * HEADS;
        int s, d;
        if (e < E_EDGES) { s = ei[e]; d = ei[E_EDGES + e]; }
        else             { s = d = e - E_EDGES; }
        float v = g_asrc[s * HEADS + h] + g_adst[d * HEADS + h];
        v = v > 0.f ? v : NEG_SLOPE * v;
        float ex = __expf(v);
        g_eexp[idx] = ex;
        atomicAdd(&g_denom[d * HEADS + h], ex);
    }
    grid_barrier(2);

    // ===== phase D: weighted aggregate (2 edges/warp, float4 atomics) =====
    {
        int gw = gt >> 5;                    // 3552 warps
        int lane = t & 31;
        int half = lane >> 4;
        int l = lane & 15;
        for (int p = gw; p < EP / 2; p += NB * NT / 32) {
            int e = p * 2 + half;
            int s, d;
            if (e < E_EDGES) { s = ei[e]; d = ei[E_EDGES + e]; }
            else             { s = d = e - E_EDGES; }
            float wl = 0.f;
            if (l < HEADS)
                wl = __fdividef(g_eexp[e * HEADS + l],
                                __ldcg(&g_denom[d * HEADS + l]) + 1e-16f);
            const float2* __restrict__ hrow = (const float2*)(g_hh16 + (size_t)s * HD);
            float a0 = 0.f, a1 = 0.f, a2 = 0.f, a3 = 0.f;
#pragma unroll
            for (int h = 0; h < HEADS; h++) {
                float wv = __shfl_sync(0xffffffffu, wl, h, 16);
                float2 pp = hrow[h * 16 + l];
                float2 f0 = __half22float2(*(const __half2*)&pp.x);
                float2 f1 = __half22float2(*(const __half2*)&pp.y);
                a0 += wv * f0.x; a1 += wv * f0.y;
                a2 += wv * f1.x; a3 += wv * f1.y;
            }
            atomicAdd((float4*)&g_agg[d * EMB + 4 * l], make_float4(a0, a1, a2, a3));
        }
    }
    grid_barrier(3);

    // ===== phase E: out = relu(emb + mean_heads(agg) + bias) =====
    for (int idx = gt; idx < (N_NODES * EMB) / 4; idx += NB * NT) {
        int c4 = idx & 15;
        float4 eb = ((const float4*)g_emb)[idx];
        float4 ag = __ldcg(((const float4*)g_agg) + idx);   // L2 (bypass stale L1)
        float4 bi = ((const float4*)bias)[c4];
        float4 r;
        r.x = fmaxf(eb.x + ag.x * (1.f / HEADS) + bi.x, 0.f);
        r.y = fmaxf(eb.y + ag.y * (1.f / HEADS) + bi.y, 0.f);
        r.z = fmaxf(eb.z + ag.z * (1.f / HEADS) + bi.z, 0.f);
        r.w = fmaxf(eb.w + ag.w * (1.f / HEADS) + bi.w, 0.f);
        ((float4*)out)[idx] = r;
    }
}

extern "C" void kernel_launch(void* const* d_in, const int* in_sizes, int n_in,
                              void* d_out, int out_size) {
    const float* x    = (const float*)d_in[0];
    const int*   ei   = (const int*)d_in[1];
    const float* We   = (const float*)d_in[2];
    const float* be   = (const float*)d_in[3];
    const float* W    = (const float*)d_in[4];
    const float* asrc = (const float*)d_in[5];
    const float* adst = (const float*)d_in[6];
    const float* bias = (const float*)d_in[7];
    float* out = (float*)d_out;

    int smem = 12 * IN_CH * 16 * sizeof(float);   // 98304 B (phase A sub-blocks)
    cudaFuncSetAttribute(k_fused, cudaFuncAttributeMaxDynamicSharedMemorySize, smem);
    k_fused<<<NB, NT, smem>>>(x, ei, We, be, W, asrc, adst, bias, out);
}

// round 15
// speedup vs baseline: 1.2883x; 1.2883x over previous
#include <cuda_runtime.h>
#include <cuda_fp16.h>
#include <cuda_bf16.h>

#define N_NODES 10000
#define E_EDGES 160000
#define EP (E_EDGES + N_NODES)   // 170000 (div by 4 -> exact edge quads)
#define IN_CH 128
#define EMB 64
#define HEADS 12
#define HD (HEADS * EMB)          // 768
#define NEG_SLOPE 0.2f
#define NPT 24                    // nodes per k_hh tile
#define NT_HH ((N_NODES + NPT - 1) / NPT)   // 417

// ---- scratch (device globals; no allocation allowed) ----
__device__ float  g_emb[N_NODES * EMB];
__device__ __half g_hh16[N_NODES * HD];        // fp16, only consumer: k_agg gather
__device__ float  g_asrc[N_NODES * HEADS];
__device__ float  g_adst[N_NODES * HEADS];
__device__ float  g_denom[N_NODES * HEADS];
__device__ float  g_eexp[EP * HEADS];
__device__ float  g_agg[N_NODES * EMB];

// ---- f32x2 packed-FMA helpers ----
__device__ __forceinline__ unsigned long long pack2(float lo, float hi) {
    unsigned long long r;
    asm("mov.b64 %0, {%1, %2};" : "=l"(r) : "f"(lo), "f"(hi));
    return r;
}
__device__ __forceinline__ void unpack2(unsigned long long v, float& lo, float& hi) {
    asm("mov.b64 {%0, %1}, %2;" : "=f"(lo), "=f"(hi) : "l"(v));
}
__device__ __forceinline__ void fma2(unsigned long long& d,
                                     unsigned long long a, unsigned long long b) {
    asm("fma.rn.f32x2 %0, %1, %2, %0;" : "+l"(d) : "l"(a), "l"(b));
}

// ---- pass 1: zero scratch (grid-stride) + emb = relu(x @ We + be) ----
__global__ void __launch_bounds__(64) k_emb(const float* __restrict__ x,
                                            const float* __restrict__ We,
                                            const float* __restrict__ be) {
    __shared__ float sx[IN_CH][16];
    int n0 = blockIdx.x * 16;
    int t = threadIdx.x;
    int gt = blockIdx.x * 64 + t;        // 0..39999

    // zero g_agg + g_denom; graph replays!
    float4 z = make_float4(0.f, 0.f, 0.f, 0.f);
    for (int i = gt; i < (N_NODES * EMB) / 4; i += 40000) ((float4*)g_agg)[i] = z;
    if (gt < (N_NODES * HEADS) / 4) ((float4*)g_denom)[gt] = z;

    for (int idx = t; idx < 16 * IN_CH; idx += 64) {
        int i = idx >> 7, k = idx & 127;
        sx[k][i] = x[(n0 + i) * IN_CH + k];
    }
    __syncthreads();
    float b = be[t];
    unsigned long long acc[8];
    unsigned long long binit = pack2(b, b);
#pragma unroll
    for (int j = 0; j < 8; j++) acc[j] = binit;
    for (int k = 0; k < IN_CH; k++) {
        float wv = We[k * EMB + t];
        unsigned long long w2 = pack2(wv, wv);
#pragma unroll
        for (int j = 0; j < 8; j++)
            fma2(acc[j], *(const unsigned long long*)&sx[k][2 * j], w2);
    }
#pragma unroll
    for (int j = 0; j < 8; j++) {
        float lo, hi;
        unpack2(acc[j], lo, hi);
        g_emb[(n0 + 2 * j) * EMB + t]     = fmaxf(lo, 0.f);
        g_emb[(n0 + 2 * j + 1) * EMB + t] = fmaxf(hi, 0.f);
    }
}

// ---- pass 2: hh = emb @ W (fp16 out) + fp32 logits, 24 nodes/block ----
__global__ void __launch_bounds__(768) k_hh(const float* __restrict__ W,
                                            const float* __restrict__ att_src,
                                            const float* __restrict__ att_dst) {
    __shared__ float se[EMB][NPT];
    __shared__ float ssrc[NPT][HEADS];
    __shared__ float sdst[NPT][HEADS];
    int n0 = blockIdx.x * NPT;
    int t = threadIdx.x;
    for (int idx = t; idx < NPT * EMB; idx += 768) {
        int i = idx >> 6, k = idx & 63;
        se[k][i] = (n0 + i < N_NODES) ? g_emb[(n0 + i) * EMB + k] : 0.f;
    }
    if (t < NPT * HEADS) {
        ((float*)ssrc)[t] = 0.f;
        ((float*)sdst)[t] = 0.f;
    }
    __syncthreads();
    unsigned long long acc[NPT / 2];
#pragma unroll
    for (int j = 0; j < NPT / 2; j++) acc[j] = 0ull;
    for (int k = 0; k < EMB; k++) {
        float wv = W[k * HD + t];
        unsigned long long w2 = pack2(wv, wv);
#pragma unroll
        for (int j = 0; j < NPT / 2; j++)
            fma2(acc[j], *(const unsigned long long*)&se[k][2 * j], w2);
    }
    float av[NPT];
#pragma unroll
    for (int j = 0; j < NPT / 2; j++) unpack2(acc[j], av[2 * j], av[2 * j + 1]);

    float as = att_src[t], ad = att_dst[t];
    int h = t >> 6;
#pragma unroll
    for (int i = 0; i < NPT; i++) {
        if (n0 + i < N_NODES)
            g_hh16[(size_t)(n0 + i) * HD + t] = __float2half_rn(av[i]);
        float ps = av[i] * as;
        float pd = av[i] * ad;
#pragma unroll
        for (int off = 16; off; off >>= 1) {
            ps += __shfl_down_sync(0xffffffffu, ps, off);
            pd += __shfl_down_sync(0xffffffffu, pd, off);
        }
        if ((t & 31) == 0) {
            atomicAdd(&ssrc[i][h], ps);
            atomicAdd(&sdst[i][h], pd);
        }
    }
    __syncthreads();
    if (t < NPT * HEADS) {
        int i = t / HEADS, hh_ = t - (t / HEADS) * HEADS;
        if (n0 + i < N_NODES) {
            g_asrc[(n0 + i) * HEADS + hh_] = ssrc[i][hh_];
            g_adst[(n0 + i) * HEADS + hh_] = sdst[i][hh_];
        }
    }
}

// ---- pass 3: thread per (edge, head): exp(leaky(logit)), atomic denom ----
__global__ void k_sum(const int* __restrict__ ei) {
    int idx = blockIdx.x * blockDim.x + threadIdx.x;
    if (idx >= EP * HEADS) return;
    int e = idx / HEADS, h = idx - e * HEADS;
    int s, d;
    if (e < E_EDGES) { s = ei[e]; d = ei[E_EDGES + e]; }
    else             { s = d = e - E_EDGES; }
    float v = g_asrc[s * HEADS + h] + g_adst[d * HEADS + h];
    v = v > 0.f ? v : NEG_SLOPE * v;
    float ex = __expf(v);
    g_eexp[idx] = ex;
    atomicAdd(&g_denom[d * HEADS + h], ex);
}

// ---- pass 4: weighted aggregate. 4 edges/warp, 8 lanes/edge,
//      8 channels/lane via float4 (LDG.128) gathers, float4 atomics ----
__global__ void __launch_bounds__(256) k_agg(const int* __restrict__ ei) {
    int w = (blockIdx.x * blockDim.x + threadIdx.x) >> 5;
    int lane = threadIdx.x & 31;
    int q = lane >> 3;                                   // edge within warp quad
    int l = lane & 7;                                    // lane within edge group
    int e = w * 4 + q;
    if (e >= EP) return;
    int s, d;
    if (e < E_EDGES) { s = ei[e]; d = ei[E_EDGES + e]; }
    else             { s = d = e - E_EDGES; }

    // softmax weights: lanes 0-7 hold heads 0-7; lanes 0-3 also hold heads 8-11
    float wa = __fdividef(g_eexp[e * HEADS + l],
                          g_denom[d * HEADS + l] + 1e-16f);
    float wb = 0.f;
    if (l < 4)
        wb = __fdividef(g_eexp[e * HEADS + 8 + l],
                        g_denom[d * HEADS + 8 + l] + 1e-16f);

    const float4* __restrict__ hrow = (const float4*)(g_hh16 + (size_t)s * HD);
    float a0 = 0.f, a1 = 0.f, a2 = 0.f, a3 = 0.f;
    float a4 = 0.f, a5 = 0.f, a6 = 0.f, a7 = 0.f;
#pragma unroll
    for (int h = 0; h < HEADS; h++) {
        float wv = (h < 8) ? __shfl_sync(0xffffffffu, wa, h, 8)
                           : __shfl_sync(0xffffffffu, wb, h - 8, 8);
        float4 p = hrow[h * 8 + l];                      // 8 halves = 8 channels
        float2 f0 = __half22float2(*(const __half2*)&p.x);
        float2 f1 = __half22float2(*(const __half2*)&p.y);
        float2 f2 = __half22float2(*(const __half2*)&p.z);
        float2 f3 = __half22float2(*(const __half2*)&p.w);
        a0 += wv * f0.x; a1 += wv * f0.y;
        a2 += wv * f1.x; a3 += wv * f1.y;
        a4 += wv * f2.x; a5 += wv * f2.y;
        a6 += wv * f3.x; a7 += wv * f3.y;
    }
    atomicAdd((float4*)&g_agg[d * EMB + 8 * l],     make_float4(a0, a1, a2, a3));
    atomicAdd((float4*)&g_agg[d * EMB + 8 * l + 4], make_float4(a4, a5, a6, a7));
}

// ---- pass 5: out = relu(emb + mean_heads(agg) + bias), float4 ----
__global__ void k_final(const float* __restrict__ bias, float* __restrict__ out) {
    int idx = blockIdx.x * blockDim.x + threadIdx.x;   // float4 index
    if (idx >= (N_NODES * EMB) / 4) return;
    int c4 = idx & 15;
    float4 eb = ((const float4*)g_emb)[idx];
    float4 ag = ((const float4*)g_agg)[idx];
    float4 bi = ((const float4*)bias)[c4];
    float4 r;
    r.x = fmaxf(eb.x + ag.x * (1.f / HEADS) + bi.x, 0.f);
    r.y = fmaxf(eb.y + ag.y * (1.f / HEADS) + bi.y, 0.f);
    r.z = fmaxf(eb.z + ag.z * (1.f / HEADS) + bi.z, 0.f);
    r.w = fmaxf(eb.w + ag.w * (1.f / HEADS) + bi.w, 0.f);
    ((float4*)out)[idx] = r;
}

extern "C" void kernel_launch(void* const* d_in, const int* in_sizes, int n_in,
                              void* d_out, int out_size) {
    const float* x    = (const float*)d_in[0];
    const int*   ei   = (const int*)d_in[1];
    const float* We   = (const float*)d_in[2];
    const float* be   = (const float*)d_in[3];
    const float* W    = (const float*)d_in[4];
    const float* asrc = (const float*)d_in[5];
    const float* adst = (const float*)d_in[6];
    const float* bias = (const float*)d_in[7];
    float* out = (float*)d_out;

    k_emb<<<N_NODES / 16, 64>>>(x, We, be);
    k_hh<<<NT_HH, 768>>>(W, asrc, adst);
    k_sum<<<(EP * HEADS + 255) / 256, 256>>>(ei);
    k_agg<<<(EP / 4 * 32 + 255) / 256, 256>>>(ei);
    k_final<<<(N_NODES * EMB / 4 + 255) / 256, 256>>>(bias, out);
}